// round 10
// baseline (speedup 1.0000x reference)
#include <cuda_runtime.h>
#include <cuda_bf16.h>
#include <cstdint>
#include <cstdio>

#define N_NODES_MAX 100000
#define E_MAX 1600000
#define HID 64
#define SCAN_BT 256
#define SCAN_NB ((N_NODES_MAX + SCAN_BT - 1) / SCAN_BT)   // 391

typedef unsigned long long ull;

// ---------------- f32x2 packed math helpers ----------------
__device__ __forceinline__ ull d_pack(float a, float b) {
    ull r; asm("mov.b64 %0, {%1, %2};" : "=l"(r) : "f"(a), "f"(b)); return r;
}
__device__ __forceinline__ void d_unpack(float& a, float& b, ull r) {
    asm("mov.b64 {%0, %1}, %2;" : "=f"(a), "=f"(b) : "l"(r));
}
__device__ __forceinline__ ull d_fma2(ull a, ull b, ull c) {
    ull r; asm("fma.rn.f32x2 %0, %1, %2, %3;" : "=l"(r) : "l"(a), "l"(b), "l"(c)); return r;
}
__device__ __forceinline__ ull d_add2(ull a, ull b) {
    ull r; asm("add.rn.f32x2 %0, %1, %2;" : "=l"(r) : "l"(a), "l"(b)); return r;
}

// ---------------- scratch (no allocations allowed) ----------------
__device__ int   g_cnt[N_NODES_MAX];
__device__ int   g_rowp[N_NODES_MAX];
__device__ int   g_cursor[N_NODES_MAX];
__device__ int   g_bsum[SCAN_NB];
__device__ int   g_csrc[E_MAX];
__device__ float g_agg[(size_t)N_NODES_MAX * HID];
__device__ float g_h[(size_t)N_NODES_MAX * HID];
__device__ float g_h2[(size_t)N_NODES_MAX * HID];
__device__ float g_uv[(size_t)N_NODES_MAX * 2 * HID];     // [N][128]: u | v
__device__ float g_wc[4][64 * 64];   // combined: 0:Wl2@W1a 1:Wr2@W1a 2:Wl2@W1b 3:Wr2@W1b
__device__ float g_bc[2][64];        // combined biases: bl2@W1a, bl2@W1b

// ---------------- CSR build (ordered scan: preserves row locality) ----------------
__global__ void zero_cnt_kernel(int N) {
    int i = blockIdx.x * blockDim.x + threadIdx.x;
    if (i < N) g_cnt[i] = 0;
}

__global__ void hist_kernel(const int* __restrict__ dst, int E) {
    int e = blockIdx.x * blockDim.x + threadIdx.x;
    if (e < E) atomicAdd(&g_cnt[dst[e]], 1);
}

__global__ void scan1_kernel(int N) {
    __shared__ int sh[SCAN_BT];
    int i = blockIdx.x * SCAN_BT + threadIdx.x;
    int v = (i < N) ? g_cnt[i] : 0;
    sh[threadIdx.x] = v;
    __syncthreads();
#pragma unroll
    for (int off = 1; off < SCAN_BT; off <<= 1) {
        int t = (threadIdx.x >= off) ? sh[threadIdx.x - off] : 0;
        __syncthreads();
        sh[threadIdx.x] += t;
        __syncthreads();
    }
    if (i < N) g_rowp[i] = sh[threadIdx.x] - v;
    if (threadIdx.x == SCAN_BT - 1) g_bsum[blockIdx.x] = sh[SCAN_BT - 1];
}

// scan3 with inlined block-offset computation (replaces scan2+scan3)
__global__ void scan23_kernel(int N) {
    __shared__ int s_off;
    // warp 0 computes sum of g_bsum[0..blockIdx.x)
    if (threadIdx.x < 32) {
        int acc = 0;
        for (int j = threadIdx.x; j < blockIdx.x; j += 32) acc += g_bsum[j];
#pragma unroll
        for (int o = 16; o > 0; o >>= 1) acc += __shfl_down_sync(0xffffffffu, acc, o);
        if (threadIdx.x == 0) s_off = acc;
    }
    __syncthreads();
    int i = blockIdx.x * SCAN_BT + threadIdx.x;
    if (i < N) {
        int r = g_rowp[i] + s_off;
        g_rowp[i] = r;
        g_cursor[i] = r;
    }
}

__global__ void fill_kernel(const int* __restrict__ src, const int* __restrict__ dst, int E) {
    int e = blockIdx.x * blockDim.x + threadIdx.x;
    if (e < E) {
        int d = dst[e];
        int pos = atomicAdd(&g_cursor[d], 1);
        g_csrc[pos] = src[e];
    }
}

// ---------------- weight combine: g_wc / g_bc (exact fp32 reassociation) ----------------
__global__ void wcomb_kernel(const float* __restrict__ Wl2, const float* __restrict__ Wr2,
                             const float* __restrict__ W1, const float* __restrict__ bl2) {
    int p = blockIdx.x;
    const float* A = (p & 1) ? Wr2 : Wl2;
    const float* B = (p & 2) ? (W1 + 64 * 64) : W1;
    __shared__ float sB[64 * 64];
    for (int i = threadIdx.x; i < 4096; i += blockDim.x) sB[i] = B[i];
    __syncthreads();

    int k  = threadIdx.x & 63;
    int jb = (threadIdx.x >> 6) * 16;
    float acc[16];
#pragma unroll
    for (int i = 0; i < 16; i++) acc[i] = 0.f;
#pragma unroll 4
    for (int m = 0; m < 64; m++) {
        float a = __ldg(A + k * 64 + m);
#pragma unroll
        for (int i = 0; i < 16; i++) acc[i] += a * sB[m * 64 + jb + i];
    }
#pragma unroll
    for (int i = 0; i < 16; i++) g_wc[p][k * 64 + jb + i] = acc[i];

    if ((p & 1) == 0 && threadIdx.x < 64) {
        int j = threadIdx.x;
        float s = 0.f;
        for (int m = 0; m < 64; m++) s += __ldg(bl2 + m) * sB[m * 64 + j];
        g_bc[p >> 1][j] = s;
    }
}

// ---------------- gather mean: agg[n] = mean_{s in in(n)} h[s] (MLP=2) ----------------
template <int F>
__global__ void gather_kernel(const float* __restrict__ h, float* __restrict__ agg, int N) {
    const int CH = F / 4;
    const int NPW = 32 / CH;
    int gt = blockIdx.x * blockDim.x + threadIdx.x;
    int warp = gt >> 5;
    int lane = threadIdx.x & 31;
    int node = warp * NPW + lane / CH;
    int c = lane % CH;
    if (node >= N) return;

    int row = g_rowp[node];
    int cnt = g_cnt[node];
    float inv = 1.0f / fmaxf((float)cnt, 1.0f);

    float4 s0 = make_float4(0.f, 0.f, 0.f, 0.f);
    float4 s1 = make_float4(0.f, 0.f, 0.f, 0.f);
    const int* lst = g_csrc + row;
    int i = 0;
    for (; i + 2 <= cnt; i += 2) {
        int a = __ldg(lst + i);
        int b = __ldg(lst + i + 1);
        float4 va = __ldg((const float4*)(h + (size_t)a * F) + c);
        float4 vb = __ldg((const float4*)(h + (size_t)b * F) + c);
        s0.x += va.x; s0.y += va.y; s0.z += va.z; s0.w += va.w;
        s1.x += vb.x; s1.y += vb.y; s1.z += vb.z; s1.w += vb.w;
    }
    if (i < cnt) {
        int a = __ldg(lst + i);
        float4 va = __ldg((const float4*)(h + (size_t)a * F) + c);
        s0.x += va.x; s0.y += va.y; s0.z += va.z; s0.w += va.w;
    }
    float4 r = make_float4((s0.x + s1.x) * inv, (s0.y + s1.y) * inv,
                           (s0.z + s1.z) * inv, (s0.w + s1.w) * inv);
    ((float4*)(agg + (size_t)node * F))[c] = r;
}

// ---------------- node transform: hout = act(mean@Wl + bl + hin@Wr), LDS.128 weights ----------------
template <int FIN>
__global__ void __launch_bounds__(128)
node_kernel(const float* __restrict__ agg, const float* __restrict__ hin,
            const float* __restrict__ Wl, const float* __restrict__ bl,
            const float* __restrict__ Wr, float* __restrict__ hout,
            int N, int do_relu, int ostride) {
    __shared__ __align__(16) float sWl[FIN * HID];
    __shared__ __align__(16) float sWr[FIN * HID];
    __shared__ __align__(16) float sb[HID];
    for (int i = threadIdx.x; i < FIN * HID; i += blockDim.x) {
        sWl[i] = Wl[i];
        sWr[i] = Wr[i];
    }
    if (threadIdx.x < HID) sb[threadIdx.x] = bl[threadIdx.x];
    __syncthreads();

    int n = blockIdx.x * blockDim.x + threadIdx.x;
    if (n >= N) return;

    ull acc[HID / 2];
    const ull* sb2 = (const ull*)sb;
#pragma unroll
    for (int j2 = 0; j2 < HID / 2; j2++) acc[j2] = sb2[j2];

    const float4* a4 = (const float4*)(agg + (size_t)n * FIN);
    const float4* h4 = (const float4*)(hin + (size_t)n * FIN);
#pragma unroll 2
    for (int k4 = 0; k4 < FIN / 4; k4++) {
        float4 av = a4[k4];
        float4 hv = h4[k4];
        float am[4] = {av.x, av.y, av.z, av.w};
        float hm[4] = {hv.x, hv.y, hv.z, hv.w};
#pragma unroll
        for (int kk = 0; kk < 4; kk++) {
            int k = k4 * 4 + kk;
            ull a2 = d_pack(am[kk], am[kk]);
            ull h2 = d_pack(hm[kk], hm[kk]);
            const ulonglong2* wl4 = (const ulonglong2*)(sWl + (size_t)k * HID);
            const ulonglong2* wr4 = (const ulonglong2*)(sWr + (size_t)k * HID);
#pragma unroll
            for (int j4 = 0; j4 < HID / 4; j4++) {
                ulonglong2 wl = wl4[j4];
                ulonglong2 wr = wr4[j4];
                acc[2 * j4 + 0] = d_fma2(a2, wl.x, acc[2 * j4 + 0]);
                acc[2 * j4 + 1] = d_fma2(a2, wl.y, acc[2 * j4 + 1]);
                acc[2 * j4 + 0] = d_fma2(h2, wr.x, acc[2 * j4 + 0]);
                acc[2 * j4 + 1] = d_fma2(h2, wr.y, acc[2 * j4 + 1]);
            }
        }
    }

    float* op = hout + (size_t)n * ostride;
#pragma unroll
    for (int j2 = 0; j2 < HID / 2; j2++) {
        float lo, hi;
        d_unpack(lo, hi, acc[j2]);
        if (do_relu) { lo = fmaxf(lo, 0.f); hi = fmaxf(hi, 0.f); }
        ((float2*)op)[j2] = make_float2(lo, hi);
    }
}

// ---------------- edge MLP: relu fused into layer 2 (no z1 array -> ~64 fewer regs) ----------------
__global__ void __launch_bounds__(128)
edge_mlp_kernel(const float* __restrict__ uv,
                const int* __restrict__ src, const int* __restrict__ dst,
                const float* __restrict__ ea,
                const float* __restrict__ W1c,   // W1 + 128*64, [8][64]
                const float* __restrict__ b1,
                const float* __restrict__ W2, const float* __restrict__ b2,
                const float* __restrict__ W3, const float* __restrict__ b3,
                float* __restrict__ out, int E) {
    __shared__ __align__(16) float sW1c[8 * 64];
    __shared__ __align__(16) float sW2[64 * 32];
    __shared__ __align__(16) float sb1[64];
    __shared__ __align__(16) float sb2[32];
    __shared__ __align__(16) float sW3[32];
    __shared__ float sb3;

    for (int i = threadIdx.x; i < 8 * 64; i += blockDim.x) sW1c[i] = W1c[i];
    for (int i = threadIdx.x; i < 64 * 32; i += blockDim.x) sW2[i] = W2[i];
    if (threadIdx.x < 64) sb1[threadIdx.x] = b1[threadIdx.x];
    if (threadIdx.x < 32) { sb2[threadIdx.x] = b2[threadIdx.x]; sW3[threadIdx.x] = W3[threadIdx.x]; }
    if (threadIdx.x == 0) sb3 = b3[0];
    __syncthreads();

    int e = blockIdx.x * blockDim.x + threadIdx.x;
    if (e >= E) return;

    int s = __ldg(src + e);
    int d = __ldg(dst + e);

    // ---- layer 1: z = u[s] + v[d] + b1 + ea @ W1c ----
    const ulonglong2* u2 = (const ulonglong2*)(uv + (size_t)s * 128);
    const ulonglong2* v2 = (const ulonglong2*)(uv + (size_t)d * 128 + 64);
    const ull* b1p = (const ull*)sb1;

    ull z[32];
#pragma unroll
    for (int q = 0; q < 16; q++) {
        ulonglong2 uu = __ldg(u2 + q);
        ulonglong2 vv = __ldg(v2 + q);
        z[2 * q + 0] = d_add2(d_add2(uu.x, vv.x), b1p[2 * q + 0]);
        z[2 * q + 1] = d_add2(d_add2(uu.y, vv.y), b1p[2 * q + 1]);
    }

    const float4* ef = (const float4*)(ea + (size_t)e * 8);
    float4 e0 = __ldg(ef);
    float4 e1 = __ldg(ef + 1);
    float efv[8] = {e0.x, e0.y, e0.z, e0.w, e1.x, e1.y, e1.z, e1.w};
#pragma unroll
    for (int k = 0; k < 8; k++) {
        ull f2 = d_pack(efv[k], efv[k]);
        const ulonglong2* w4 = (const ulonglong2*)(sW1c + k * 64);
#pragma unroll
        for (int j4 = 0; j4 < 16; j4++) {
            ulonglong2 w = w4[j4];
            z[2 * j4 + 0] = d_fma2(f2, w.x, z[2 * j4 + 0]);
            z[2 * j4 + 1] = d_fma2(f2, w.y, z[2 * j4 + 1]);
        }
    }

    // ---- layer 2 with fused relu: a2 += relu(z_k) * W2[k][:] ----
    ull a2[16];
    const ull* b2p = (const ull*)sb2;
#pragma unroll
    for (int j2 = 0; j2 < 16; j2++) a2[j2] = b2p[j2];
#pragma unroll
    for (int j2 = 0; j2 < 32; j2++) {           // z pair index: k = 2*j2, 2*j2+1
        float lo, hi;
        d_unpack(lo, hi, z[j2]);
        lo = fmaxf(lo, 0.f); hi = fmaxf(hi, 0.f);
        ull f2a = d_pack(lo, lo);
        ull f2b = d_pack(hi, hi);
        const ulonglong2* w4a = (const ulonglong2*)(sW2 + (2 * j2 + 0) * 32);
        const ulonglong2* w4b = (const ulonglong2*)(sW2 + (2 * j2 + 1) * 32);
#pragma unroll
        for (int j4 = 0; j4 < 8; j4++) {
            ulonglong2 wa = w4a[j4];
            ulonglong2 wb = w4b[j4];
            a2[2 * j4 + 0] = d_fma2(f2a, wa.x, a2[2 * j4 + 0]);
            a2[2 * j4 + 1] = d_fma2(f2a, wa.y, a2[2 * j4 + 1]);
            a2[2 * j4 + 0] = d_fma2(f2b, wb.x, a2[2 * j4 + 0]);
            a2[2 * j4 + 1] = d_fma2(f2b, wb.y, a2[2 * j4 + 1]);
        }
    }

    // ---- relu + layer 3 + sigmoid ----
    float zz = sb3;
#pragma unroll
    for (int j2 = 0; j2 < 16; j2++) {
        float lo, hi;
        d_unpack(lo, hi, a2[j2]);
        zz += fmaxf(lo, 0.f) * sW3[2 * j2] + fmaxf(hi, 0.f) * sW3[2 * j2 + 1];
    }

    out[e] = 1.0f / (1.0f + __expf(-zz));
}

// ---------------- host launcher ----------------
extern "C" void kernel_launch(void* const* d_in, const int* in_sizes, int n_in,
                              void* d_out, int out_size) {
    const float* x   = (const float*)d_in[0];
    const int*   ei  = (const int*)d_in[1];
    const float* ea  = (const float*)d_in[2];
    const float* Wl0 = (const float*)d_in[3];
    const float* bl0 = (const float*)d_in[4];
    const float* Wr0 = (const float*)d_in[5];
    const float* Wl1 = (const float*)d_in[6];
    const float* bl1 = (const float*)d_in[7];
    const float* Wr1 = (const float*)d_in[8];
    const float* Wl2 = (const float*)d_in[9];
    const float* bl2 = (const float*)d_in[10];
    const float* Wr2 = (const float*)d_in[11];
    const float* W1  = (const float*)d_in[12];
    const float* b1  = (const float*)d_in[13];
    const float* W2  = (const float*)d_in[14];
    const float* b2  = (const float*)d_in[15];
    const float* W3  = (const float*)d_in[16];
    const float* b3  = (const float*)d_in[17];
    float* out = (float*)d_out;

    const int N = in_sizes[0] / 32;     // 100000
    const int E = in_sizes[1] / 2;      // 1600000
    const int* src = ei;
    const int* dst = ei + E;

    float *p_agg = nullptr, *p_h = nullptr, *p_h2 = nullptr, *p_uv = nullptr;
    float *p_wc = nullptr, *p_bc = nullptr;
    cudaGetSymbolAddress((void**)&p_agg, g_agg);
    cudaGetSymbolAddress((void**)&p_h,   g_h);
    cudaGetSymbolAddress((void**)&p_h2,  g_h2);
    cudaGetSymbolAddress((void**)&p_uv,  g_uv);
    cudaGetSymbolAddress((void**)&p_wc,  g_wc);
    cudaGetSymbolAddress((void**)&p_bc,  g_bc);

    const int BT = 256;
    const int nb = (N + SCAN_BT - 1) / SCAN_BT;

    // ---- CSR build (launch idx 0-4) ----
    zero_cnt_kernel<<<(N + BT - 1) / BT, BT>>>(N);                 // 0
    hist_kernel<<<(E + BT - 1) / BT, BT>>>(dst, E);                // 1
    scan1_kernel<<<nb, SCAN_BT>>>(N);                              // 2
    scan23_kernel<<<nb, SCAN_BT>>>(N);                             // 3
    fill_kernel<<<(E + BT - 1) / BT, BT>>>(src, dst, E);           // 4

    // ---- layer 0 ----  (gather32 = launch idx 5: ncu -s 5 captures it)
    {
        const int NPW = 32 / (32 / 4);
        int warps = (N + NPW - 1) / NPW;
        gather_kernel<32><<<(warps * 32 + BT - 1) / BT, BT>>>(x, p_agg, N);      // 5
        node_kernel<32><<<(N + 127) / 128, 128>>>(p_agg, x, Wl0, bl0, Wr0, p_h, N, 1, HID);
    }

    // ---- combined layer2+edge-layer1 weights (needed before uv kernels) ----
    wcomb_kernel<<<4, 256>>>(Wl2, Wr2, W1, bl2);

    // ---- layer 1 ----
    {
        const int NPW = 32 / (64 / 4);
        int warps = (N + NPW - 1) / NPW;
        gather_kernel<64><<<(warps * 32 + BT - 1) / BT, BT>>>(p_h, p_agg, N);
        node_kernel<64><<<(N + 127) / 128, 128>>>(p_agg, p_h, Wl1, bl1, Wr1, p_h2, N, 1, HID);
    }
    // ---- layer 2 fused with u/v ----
    {
        const int NPW = 32 / (64 / 4);
        int warps = (N + NPW - 1) / NPW;
        gather_kernel<64><<<(warps * 32 + BT - 1) / BT, BT>>>(p_h2, p_agg, N);
        node_kernel<64><<<(N + 127) / 128, 128>>>(p_agg, p_h2, p_wc + 0 * 4096, p_bc + 0,
                                                  p_wc + 1 * 4096, p_uv, N, 0, 128);
        node_kernel<64><<<(N + 127) / 128, 128>>>(p_agg, p_h2, p_wc + 2 * 4096, p_bc + 64,
                                                  p_wc + 3 * 4096, p_uv + 64, N, 0, 128);
    }

    // ---- edge MLP ----
    edge_mlp_kernel<<<(E + 127) / 128, 128>>>(p_uv, src, dst, ea,
                                              W1 + 128 * 64, b1, W2, b2, W3, b3,
                                              out, E);
}

// round 11
// speedup vs baseline: 1.0030x; 1.0030x over previous
#include <cuda_runtime.h>
#include <cuda_bf16.h>
#include <cstdint>
#include <cstdio>

#define N_NODES_MAX 100000
#define E_MAX 1600000
#define HID 64
#define SCAN_BT 256
#define SCAN_NB ((N_NODES_MAX + SCAN_BT - 1) / SCAN_BT)   // 391

typedef unsigned long long ull;

// ---------------- f32x2 packed math helpers ----------------
__device__ __forceinline__ ull d_pack(float a, float b) {
    ull r; asm("mov.b64 %0, {%1, %2};" : "=l"(r) : "f"(a), "f"(b)); return r;
}
__device__ __forceinline__ void d_unpack(float& a, float& b, ull r) {
    asm("mov.b64 {%0, %1}, %2;" : "=f"(a), "=f"(b) : "l"(r));
}
__device__ __forceinline__ ull d_fma2(ull a, ull b, ull c) {
    ull r; asm("fma.rn.f32x2 %0, %1, %2, %3;" : "=l"(r) : "l"(a), "l"(b), "l"(c)); return r;
}
__device__ __forceinline__ ull d_add2(ull a, ull b) {
    ull r; asm("add.rn.f32x2 %0, %1, %2;" : "=l"(r) : "l"(a), "l"(b)); return r;
}

// ---------------- scratch (no allocations allowed) ----------------
__device__ int   g_cnt[N_NODES_MAX];
__device__ int   g_rowp[N_NODES_MAX];
__device__ int   g_cursor[N_NODES_MAX];
__device__ int   g_bsum[SCAN_NB];
__device__ int   g_csrc[E_MAX];
__device__ float g_agg[(size_t)N_NODES_MAX * HID];
__device__ float g_h[(size_t)N_NODES_MAX * HID];
__device__ float g_h2[(size_t)N_NODES_MAX * HID];
__device__ float g_uv[(size_t)N_NODES_MAX * 2 * HID];     // [N][128]: u | v
__device__ float g_wc[4][64 * 64];   // combined: 0:Wl2@W1a 1:Wr2@W1a 2:Wl2@W1b 3:Wr2@W1b
__device__ float g_bc[2][64];        // combined biases: bl2@W1a, bl2@W1b

// ---------------- CSR build (ordered scan: preserves row locality) ----------------
__global__ void zero_cnt_kernel(int N) {
    int i = blockIdx.x * blockDim.x + threadIdx.x;
    if (i < N) g_cnt[i] = 0;
}

__global__ void hist_kernel(const int* __restrict__ dst, int E) {
    int e = blockIdx.x * blockDim.x + threadIdx.x;
    if (e < E) atomicAdd(&g_cnt[dst[e]], 1);
}

__global__ void scan1_kernel(int N) {
    __shared__ int sh[SCAN_BT];
    int i = blockIdx.x * SCAN_BT + threadIdx.x;
    int v = (i < N) ? g_cnt[i] : 0;
    sh[threadIdx.x] = v;
    __syncthreads();
#pragma unroll
    for (int off = 1; off < SCAN_BT; off <<= 1) {
        int t = (threadIdx.x >= off) ? sh[threadIdx.x - off] : 0;
        __syncthreads();
        sh[threadIdx.x] += t;
        __syncthreads();
    }
    if (i < N) g_rowp[i] = sh[threadIdx.x] - v;
    if (threadIdx.x == SCAN_BT - 1) g_bsum[blockIdx.x] = sh[SCAN_BT - 1];
}

// scan3 with inlined block-offset computation (replaces scan2+scan3)
__global__ void scan23_kernel(int N) {
    __shared__ int s_off;
    // warp 0 computes sum of g_bsum[0..blockIdx.x)
    if (threadIdx.x < 32) {
        int acc = 0;
        for (int j = threadIdx.x; j < blockIdx.x; j += 32) acc += g_bsum[j];
#pragma unroll
        for (int o = 16; o > 0; o >>= 1) acc += __shfl_down_sync(0xffffffffu, acc, o);
        if (threadIdx.x == 0) s_off = acc;
    }
    __syncthreads();
    int i = blockIdx.x * SCAN_BT + threadIdx.x;
    if (i < N) {
        int r = g_rowp[i] + s_off;
        g_rowp[i] = r;
        g_cursor[i] = r;
    }
}

__global__ void fill_kernel(const int* __restrict__ src, const int* __restrict__ dst, int E) {
    int e = blockIdx.x * blockDim.x + threadIdx.x;
    if (e < E) {
        int d = dst[e];
        int pos = atomicAdd(&g_cursor[d], 1);
        g_csrc[pos] = src[e];
    }
}

// ---------------- weight combine: g_wc / g_bc (exact fp32 reassociation) ----------------
__global__ void wcomb_kernel(const float* __restrict__ Wl2, const float* __restrict__ Wr2,
                             const float* __restrict__ W1, const float* __restrict__ bl2) {
    int p = blockIdx.x;
    const float* A = (p & 1) ? Wr2 : Wl2;
    const float* B = (p & 2) ? (W1 + 64 * 64) : W1;
    __shared__ float sB[64 * 64];
    for (int i = threadIdx.x; i < 4096; i += blockDim.x) sB[i] = B[i];
    __syncthreads();

    int k  = threadIdx.x & 63;
    int jb = (threadIdx.x >> 6) * 16;
    float acc[16];
#pragma unroll
    for (int i = 0; i < 16; i++) acc[i] = 0.f;
#pragma unroll 4
    for (int m = 0; m < 64; m++) {
        float a = __ldg(A + k * 64 + m);
#pragma unroll
        for (int i = 0; i < 16; i++) acc[i] += a * sB[m * 64 + jb + i];
    }
#pragma unroll
    for (int i = 0; i < 16; i++) g_wc[p][k * 64 + jb + i] = acc[i];

    if ((p & 1) == 0 && threadIdx.x < 64) {
        int j = threadIdx.x;
        float s = 0.f;
        for (int m = 0; m < 64; m++) s += __ldg(bl2 + m) * sB[m * 64 + j];
        g_bc[p >> 1][j] = s;
    }
}

// ---------------- gather mean: agg[n] = mean_{s in in(n)} h[s] (MLP=2) ----------------
template <int F>
__global__ void gather_kernel(const float* __restrict__ h, float* __restrict__ agg, int N) {
    const int CH = F / 4;
    const int NPW = 32 / CH;
    int gt = blockIdx.x * blockDim.x + threadIdx.x;
    int warp = gt >> 5;
    int lane = threadIdx.x & 31;
    int node = warp * NPW + lane / CH;
    int c = lane % CH;
    if (node >= N) return;

    int row = g_rowp[node];
    int cnt = g_cnt[node];
    float inv = 1.0f / fmaxf((float)cnt, 1.0f);

    float4 s0 = make_float4(0.f, 0.f, 0.f, 0.f);
    float4 s1 = make_float4(0.f, 0.f, 0.f, 0.f);
    const int* lst = g_csrc + row;
    int i = 0;
    for (; i + 2 <= cnt; i += 2) {
        int a = __ldg(lst + i);
        int b = __ldg(lst + i + 1);
        float4 va = __ldg((const float4*)(h + (size_t)a * F) + c);
        float4 vb = __ldg((const float4*)(h + (size_t)b * F) + c);
        s0.x += va.x; s0.y += va.y; s0.z += va.z; s0.w += va.w;
        s1.x += vb.x; s1.y += vb.y; s1.z += vb.z; s1.w += vb.w;
    }
    if (i < cnt) {
        int a = __ldg(lst + i);
        float4 va = __ldg((const float4*)(h + (size_t)a * F) + c);
        s0.x += va.x; s0.y += va.y; s0.z += va.z; s0.w += va.w;
    }
    float4 r = make_float4((s0.x + s1.x) * inv, (s0.y + s1.y) * inv,
                           (s0.z + s1.z) * inv, (s0.w + s1.w) * inv);
    ((float4*)(agg + (size_t)node * F))[c] = r;
}

// ---------------- node transform: hout = act(mean@Wl + bl + hin@Wr), LDS.128 weights ----------------
template <int FIN>
__global__ void __launch_bounds__(128)
node_kernel(const float* __restrict__ agg, const float* __restrict__ hin,
            const float* __restrict__ Wl, const float* __restrict__ bl,
            const float* __restrict__ Wr, float* __restrict__ hout,
            int N, int do_relu, int ostride) {
    __shared__ __align__(16) float sWl[FIN * HID];
    __shared__ __align__(16) float sWr[FIN * HID];
    __shared__ __align__(16) float sb[HID];
    for (int i = threadIdx.x; i < FIN * HID; i += blockDim.x) {
        sWl[i] = Wl[i];
        sWr[i] = Wr[i];
    }
    if (threadIdx.x < HID) sb[threadIdx.x] = bl[threadIdx.x];
    __syncthreads();

    int n = blockIdx.x * blockDim.x + threadIdx.x;
    if (n >= N) return;

    ull acc[HID / 2];
    const ull* sb2 = (const ull*)sb;
#pragma unroll
    for (int j2 = 0; j2 < HID / 2; j2++) acc[j2] = sb2[j2];

    const float4* a4 = (const float4*)(agg + (size_t)n * FIN);
    const float4* h4 = (const float4*)(hin + (size_t)n * FIN);
#pragma unroll 2
    for (int k4 = 0; k4 < FIN / 4; k4++) {
        float4 av = a4[k4];
        float4 hv = h4[k4];
        float am[4] = {av.x, av.y, av.z, av.w};
        float hm[4] = {hv.x, hv.y, hv.z, hv.w};
#pragma unroll
        for (int kk = 0; kk < 4; kk++) {
            int k = k4 * 4 + kk;
            ull a2 = d_pack(am[kk], am[kk]);
            ull h2 = d_pack(hm[kk], hm[kk]);
            const ulonglong2* wl4 = (const ulonglong2*)(sWl + (size_t)k * HID);
            const ulonglong2* wr4 = (const ulonglong2*)(sWr + (size_t)k * HID);
#pragma unroll
            for (int j4 = 0; j4 < HID / 4; j4++) {
                ulonglong2 wl = wl4[j4];
                ulonglong2 wr = wr4[j4];
                acc[2 * j4 + 0] = d_fma2(a2, wl.x, acc[2 * j4 + 0]);
                acc[2 * j4 + 1] = d_fma2(a2, wl.y, acc[2 * j4 + 1]);
                acc[2 * j4 + 0] = d_fma2(h2, wr.x, acc[2 * j4 + 0]);
                acc[2 * j4 + 1] = d_fma2(h2, wr.y, acc[2 * j4 + 1]);
            }
        }
    }

    float* op = hout + (size_t)n * ostride;
#pragma unroll
    for (int j2 = 0; j2 < HID / 2; j2++) {
        float lo, hi;
        d_unpack(lo, hi, acc[j2]);
        if (do_relu) { lo = fmaxf(lo, 0.f); hi = fmaxf(hi, 0.f); }
        ((float2*)op)[j2] = make_float2(lo, hi);
    }
}

// ---------------- edge MLP: relu fused into layer 2 (no z1 array -> ~64 fewer regs) ----------------
__global__ void __launch_bounds__(128)
edge_mlp_kernel(const float* __restrict__ uv,
                const int* __restrict__ src, const int* __restrict__ dst,
                const float* __restrict__ ea,
                const float* __restrict__ W1c,   // W1 + 128*64, [8][64]
                const float* __restrict__ b1,
                const float* __restrict__ W2, const float* __restrict__ b2,
                const float* __restrict__ W3, const float* __restrict__ b3,
                float* __restrict__ out, int E) {
    __shared__ __align__(16) float sW1c[8 * 64];
    __shared__ __align__(16) float sW2[64 * 32];
    __shared__ __align__(16) float sb1[64];
    __shared__ __align__(16) float sb2[32];
    __shared__ __align__(16) float sW3[32];
    __shared__ float sb3;

    for (int i = threadIdx.x; i < 8 * 64; i += blockDim.x) sW1c[i] = W1c[i];
    for (int i = threadIdx.x; i < 64 * 32; i += blockDim.x) sW2[i] = W2[i];
    if (threadIdx.x < 64) sb1[threadIdx.x] = b1[threadIdx.x];
    if (threadIdx.x < 32) { sb2[threadIdx.x] = b2[threadIdx.x]; sW3[threadIdx.x] = W3[threadIdx.x]; }
    if (threadIdx.x == 0) sb3 = b3[0];
    __syncthreads();

    int e = blockIdx.x * blockDim.x + threadIdx.x;
    if (e >= E) return;

    int s = __ldg(src + e);
    int d = __ldg(dst + e);

    // ---- layer 1: z = u[s] + v[d] + b1 + ea @ W1c ----
    const ulonglong2* u2 = (const ulonglong2*)(uv + (size_t)s * 128);
    const ulonglong2* v2 = (const ulonglong2*)(uv + (size_t)d * 128 + 64);
    const ull* b1p = (const ull*)sb1;

    ull z[32];
#pragma unroll
    for (int q = 0; q < 16; q++) {
        ulonglong2 uu = __ldg(u2 + q);
        ulonglong2 vv = __ldg(v2 + q);
        z[2 * q + 0] = d_add2(d_add2(uu.x, vv.x), b1p[2 * q + 0]);
        z[2 * q + 1] = d_add2(d_add2(uu.y, vv.y), b1p[2 * q + 1]);
    }

    const float4* ef = (const float4*)(ea + (size_t)e * 8);
    float4 e0 = __ldg(ef);
    float4 e1 = __ldg(ef + 1);
    float efv[8] = {e0.x, e0.y, e0.z, e0.w, e1.x, e1.y, e1.z, e1.w};
#pragma unroll
    for (int k = 0; k < 8; k++) {
        ull f2 = d_pack(efv[k], efv[k]);
        const ulonglong2* w4 = (const ulonglong2*)(sW1c + k * 64);
#pragma unroll
        for (int j4 = 0; j4 < 16; j4++) {
            ulonglong2 w = w4[j4];
            z[2 * j4 + 0] = d_fma2(f2, w.x, z[2 * j4 + 0]);
            z[2 * j4 + 1] = d_fma2(f2, w.y, z[2 * j4 + 1]);
        }
    }

    // ---- layer 2 with fused relu: a2 += relu(z_k) * W2[k][:] ----
    ull a2[16];
    const ull* b2p = (const ull*)sb2;
#pragma unroll
    for (int j2 = 0; j2 < 16; j2++) a2[j2] = b2p[j2];
#pragma unroll
    for (int j2 = 0; j2 < 32; j2++) {           // z pair index: k = 2*j2, 2*j2+1
        float lo, hi;
        d_unpack(lo, hi, z[j2]);
        lo = fmaxf(lo, 0.f); hi = fmaxf(hi, 0.f);
        ull f2a = d_pack(lo, lo);
        ull f2b = d_pack(hi, hi);
        const ulonglong2* w4a = (const ulonglong2*)(sW2 + (2 * j2 + 0) * 32);
        const ulonglong2* w4b = (const ulonglong2*)(sW2 + (2 * j2 + 1) * 32);
#pragma unroll
        for (int j4 = 0; j4 < 8; j4++) {
            ulonglong2 wa = w4a[j4];
            ulonglong2 wb = w4b[j4];
            a2[2 * j4 + 0] = d_fma2(f2a, wa.x, a2[2 * j4 + 0]);
            a2[2 * j4 + 1] = d_fma2(f2a, wa.y, a2[2 * j4 + 1]);
            a2[2 * j4 + 0] = d_fma2(f2b, wb.x, a2[2 * j4 + 0]);
            a2[2 * j4 + 1] = d_fma2(f2b, wb.y, a2[2 * j4 + 1]);
        }
    }

    // ---- relu + layer 3 + sigmoid ----
    float zz = sb3;
#pragma unroll
    for (int j2 = 0; j2 < 16; j2++) {
        float lo, hi;
        d_unpack(lo, hi, a2[j2]);
        zz += fmaxf(lo, 0.f) * sW3[2 * j2] + fmaxf(hi, 0.f) * sW3[2 * j2 + 1];
    }

    out[e] = 1.0f / (1.0f + __expf(-zz));
}

// ---------------- host launcher ----------------
extern "C" void kernel_launch(void* const* d_in, const int* in_sizes, int n_in,
                              void* d_out, int out_size) {
    const float* x   = (const float*)d_in[0];
    const int*   ei  = (const int*)d_in[1];
    const float* ea  = (const float*)d_in[2];
    const float* Wl0 = (const float*)d_in[3];
    const float* bl0 = (const float*)d_in[4];
    const float* Wr0 = (const float*)d_in[5];
    const float* Wl1 = (const float*)d_in[6];
    const float* bl1 = (const float*)d_in[7];
    const float* Wr1 = (const float*)d_in[8];
    const float* Wl2 = (const float*)d_in[9];
    const float* bl2 = (const float*)d_in[10];
    const float* Wr2 = (const float*)d_in[11];
    const float* W1  = (const float*)d_in[12];
    const float* b1  = (const float*)d_in[13];
    const float* W2  = (const float*)d_in[14];
    const float* b2  = (const float*)d_in[15];
    const float* W3  = (const float*)d_in[16];
    const float* b3  = (const float*)d_in[17];
    float* out = (float*)d_out;

    const int N = in_sizes[0] / 32;     // 100000
    const int E = in_sizes[1] / 2;      // 1600000
    const int* src = ei;
    const int* dst = ei + E;

    float *p_agg = nullptr, *p_h = nullptr, *p_h2 = nullptr, *p_uv = nullptr;
    float *p_wc = nullptr, *p_bc = nullptr;
    cudaGetSymbolAddress((void**)&p_agg, g_agg);
    cudaGetSymbolAddress((void**)&p_h,   g_h);
    cudaGetSymbolAddress((void**)&p_h2,  g_h2);
    cudaGetSymbolAddress((void**)&p_uv,  g_uv);
    cudaGetSymbolAddress((void**)&p_wc,  g_wc);
    cudaGetSymbolAddress((void**)&p_bc,  g_bc);

    const int BT = 256;
    const int nb = (N + SCAN_BT - 1) / SCAN_BT;

    // ---- CSR build (launch idx 0-4) ----
    zero_cnt_kernel<<<(N + BT - 1) / BT, BT>>>(N);                 // 0
    hist_kernel<<<(E + BT - 1) / BT, BT>>>(dst, E);                // 1
    scan1_kernel<<<nb, SCAN_BT>>>(N);                              // 2
    scan23_kernel<<<nb, SCAN_BT>>>(N);                             // 3
    fill_kernel<<<(E + BT - 1) / BT, BT>>>(src, dst, E);           // 4

    // ---- layer 0 ----  (gather32 = launch idx 5: ncu -s 5 captures it)
    {
        const int NPW = 32 / (32 / 4);
        int warps = (N + NPW - 1) / NPW;
        gather_kernel<32><<<(warps * 32 + BT - 1) / BT, BT>>>(x, p_agg, N);      // 5
        node_kernel<32><<<(N + 127) / 128, 128>>>(p_agg, x, Wl0, bl0, Wr0, p_h, N, 1, HID);
    }

    // ---- combined layer2+edge-layer1 weights (needed before uv kernels) ----
    wcomb_kernel<<<4, 256>>>(Wl2, Wr2, W1, bl2);

    // ---- layer 1 ----
    {
        const int NPW = 32 / (64 / 4);
        int warps = (N + NPW - 1) / NPW;
        gather_kernel<64><<<(warps * 32 + BT - 1) / BT, BT>>>(p_h, p_agg, N);
        node_kernel<64><<<(N + 127) / 128, 128>>>(p_agg, p_h, Wl1, bl1, Wr1, p_h2, N, 1, HID);
    }
    // ---- layer 2 fused with u/v ----
    {
        const int NPW = 32 / (64 / 4);
        int warps = (N + NPW - 1) / NPW;
        gather_kernel<64><<<(warps * 32 + BT - 1) / BT, BT>>>(p_h2, p_agg, N);
        node_kernel<64><<<(N + 127) / 128, 128>>>(p_agg, p_h2, p_wc + 0 * 4096, p_bc + 0,
                                                  p_wc + 1 * 4096, p_uv, N, 0, 128);
        node_kernel<64><<<(N + 127) / 128, 128>>>(p_agg, p_h2, p_wc + 2 * 4096, p_bc + 64,
                                                  p_wc + 3 * 4096, p_uv + 64, N, 0, 128);
    }

    // ---- edge MLP ----
    edge_mlp_kernel<<<(E + 127) / 128, 128>>>(p_uv, src, dst, ea,
                                              W1 + 128 * 64, b1, W2, b2, W3, b3,
                                              out, E);
}